// round 6
// baseline (speedup 1.0000x reference)
#include <cuda_runtime.h>
#include <cuda_bf16.h>

#define HH 200
#define WW 320
#define CC 256
#define RR 128
#define MM 14
#define HWSZ (HH*WW)
#define NBIN (MM*MM)            // 196
#define NSAMP 512               // per bin: 128 rois * 4 pts
#define MARGIN 0.0625f

// bf16 transposed feature [H*W, C] and per-sample screened maxima.
__device__ __align__(16) __nv_bfloat16 g_featB[HWSZ * CC];
__device__ float g_sval[NBIN * NSAMP];
__device__ __align__(16) float g_bin[NBIN];

// -------------------------------------------------------------------------
// Transpose + convert: [C, H*W] fp32 -> [H*W, C] bf16.
// Tile: 64 channels x 32 hw positions. Block (32,8).
__global__ void convert_kernel(const float* __restrict__ f) {
    __shared__ float tile[64][33];
    const int hw0 = blockIdx.x * 32;
    const int c0  = blockIdx.y * 64;
    const int tx = threadIdx.x;   // 0..31 (hw within tile on load, c-pair on store)
    const int ty = threadIdx.y;   // 0..7
#pragma unroll
    for (int j = 0; j < 8; j++) {
        const int c = ty + j * 8;                 // 0..63
        tile[c][tx] = f[(size_t)(c0 + c) * HWSZ + hw0 + tx];
    }
    __syncthreads();
#pragma unroll
    for (int i = 0; i < 4; i++) {
        const int row = ty + i * 8;               // hw row 0..31
        const float lo = tile[2 * tx][row];
        const float hi = tile[2 * tx + 1][row];
        __nv_bfloat162 v = __floats2bfloat162_rn(lo, hi);
        *(__nv_bfloat162*)(g_featB + (size_t)(hw0 + row) * CC + c0 + 2 * tx) = v;
    }
}

// -------------------------------------------------------------------------
__device__ __forceinline__ float2 b2f(unsigned u) {
    return make_float2(__uint_as_float(u << 16), __uint_as_float(u & 0xffff0000u));
}

__device__ __forceinline__ void sample_geom(const float* __restrict__ rois,
                                            int r, int pt, int m, int n,
                                            int& i11, int& i12, int& i21, int& i22,
                                            float& wxh, float& wxl, float& wyh, float& wyl) {
    const float ry = rois[r * 4 + 0];
    const float rx = rois[r * 4 + 1];
    const float sh = (rois[r * 4 + 2] - ry) / 14.0f;
    const float sw = (rois[r * 4 + 3] - rx) / 14.0f;
    const float fr = (pt & 2) ? (2.0f / 3.0f) : (1.0f / 3.0f);
    const float fc = (pt & 1) ? (2.0f / 3.0f) : (1.0f / 3.0f);
    const float y = (ry + sh * (float)m) + sh * fr;
    const float x = (rx + sw * (float)n) + sw * fc;
    const int yf = (int)floorf(y);
    const int y1 = min(max(yf, 0), HH - 1);
    const int y2 = min(max(yf + 1, 0), HH - 1);
    const int xf = (int)floorf(x);
    const int x1 = min(max(xf, 0), WW - 1);
    const int x2 = min(max(xf + 1, 0), WW - 1);
    // Reference computes weights from the *clamped* corner indices.
    wyl = y - (float)y1;
    wyh = (float)y2 - y;
    wxl = x - (float)x1;
    wxh = (float)x2 - x;
    i11 = y1 * WW + x1;  i12 = y1 * WW + x2;
    i21 = y2 * WW + x1;  i22 = y2 * WW + x2;
}

// Screening: bf16 gather; writes per-sample channel-max to g_sval.
// grid (196 bins, 8 roi-chunks of 16), block 256 = 8 warps; warp handles
// tasks t = warp + 8k (k<8), task = (roi_local, pt).
__global__ void screen_kernel(const float* __restrict__ rois) {
    const int bin  = blockIdx.x;
    const int m    = bin / MM;
    const int n    = bin % MM;
    const int warp = threadIdx.x >> 5;
    const int lane = threadIdx.x & 31;
    const int r0   = blockIdx.y * 16;

    for (int t = warp; t < 64; t += 8) {
        const int r  = r0 + (t >> 2);
        const int pt = t & 3;
        int i11, i12, i21, i22; float wxh, wxl, wyh, wyl;
        sample_geom(rois, r, pt, m, n, i11, i12, i21, i22, wxh, wxl, wyh, wyl);

        // 32 lanes x 16B = 512B = all 256 bf16 channels of a pixel.
        const uint4 A = ((const uint4*)(g_featB + (size_t)i11 * CC))[lane];
        const uint4 B = ((const uint4*)(g_featB + (size_t)i12 * CC))[lane];
        const uint4 Cv = ((const uint4*)(g_featB + (size_t)i21 * CC))[lane];
        const uint4 D = ((const uint4*)(g_featB + (size_t)i22 * CC))[lane];

        float vmax = __int_as_float(0xff800000);
        const unsigned au[4] = {A.x, A.y, A.z, A.w};
        const unsigned bu[4] = {B.x, B.y, B.z, B.w};
        const unsigned cu[4] = {Cv.x, Cv.y, Cv.z, Cv.w};
        const unsigned du[4] = {D.x, D.y, D.z, D.w};
#pragma unroll
        for (int i = 0; i < 4; i++) {
            const float2 a = b2f(au[i]), b = b2f(bu[i]);
            const float2 c = b2f(cu[i]), d = b2f(du[i]);
            float p, q, v;
            p = fmaf(a.x, wxh, b.x * wxl);
            q = fmaf(c.x, wxh, d.x * wxl);
            v = fmaf(p, wyh, q * wyl);
            vmax = fmaxf(vmax, v);
            p = fmaf(a.y, wxh, b.y * wxl);
            q = fmaf(c.y, wxh, d.y * wxl);
            v = fmaf(p, wyh, q * wyl);
            vmax = fmaxf(vmax, v);
        }
#pragma unroll
        for (int o = 16; o > 0; o >>= 1)
            vmax = fmaxf(vmax, __shfl_xor_sync(0xffffffffu, vmax, o));
        if (lane == 0)
            g_sval[bin * NSAMP + r * 4 + pt] = vmax;
    }
}

// -------------------------------------------------------------------------
// Refine: per bin, find screened max, exactly re-evaluate candidates within
// MARGIN from the ORIGINAL fp32 [C,H,W] tensor (bitwise-exact fp32 result).
__global__ void refine_kernel(const float* __restrict__ feature,
                              const float* __restrict__ rois) {
    __shared__ float s[NSAMP];
    __shared__ float sred[8];
    const int bin  = blockIdx.x;
    const int m    = bin / MM;
    const int n    = bin % MM;
    const int tid  = threadIdx.x;
    const int warp = tid >> 5;
    const int lane = tid & 31;

    float sm = fmaxf(g_sval[bin * NSAMP + tid], g_sval[bin * NSAMP + tid + 256]);
    s[tid]       = g_sval[bin * NSAMP + tid];
    s[tid + 256] = g_sval[bin * NSAMP + tid + 256];
#pragma unroll
    for (int o = 16; o > 0; o >>= 1)
        sm = fmaxf(sm, __shfl_xor_sync(0xffffffffu, sm, o));
    if (lane == 0) sred[warp] = sm;
    __syncthreads();
    float smax = sred[0];
#pragma unroll
    for (int i = 1; i < 8; i++) smax = fmaxf(smax, sred[i]);
    const float thr = smax - MARGIN;

    float ex = __int_as_float(0xff800000);
    for (int t = warp; t < NSAMP; t += 8) {
        if (s[t] < thr) continue;
        const int r  = t >> 2;
        const int pt = t & 3;
        int i11, i12, i21, i22; float wxh, wxl, wyh, wyl;
        sample_geom(rois, r, pt, m, n, i11, i12, i21, i22, wxh, wxl, wyh, wyl);
#pragma unroll
        for (int k = 0; k < 8; k++) {
            const int c = lane + k * 32;
            const float* base = feature + (size_t)c * HWSZ;
            const float a = __ldg(base + i11);
            const float b = __ldg(base + i12);
            const float cc = __ldg(base + i21);
            const float d = __ldg(base + i22);
            const float p = fmaf(a, wxh, b * wxl);
            const float q = fmaf(cc, wxh, d * wxl);
            ex = fmaxf(ex, fmaf(p, wyh, q * wyl));
        }
    }
#pragma unroll
    for (int o = 16; o > 0; o >>= 1)
        ex = fmaxf(ex, __shfl_xor_sync(0xffffffffu, ex, o));
    __syncthreads();
    if (lane == 0) sred[warp] = ex;
    __syncthreads();
    if (tid == 0) {
        float v = sred[0];
#pragma unroll
        for (int i = 1; i < 8; i++) v = fmaxf(v, sred[i]);
        g_bin[bin] = v;
    }
}

// -------------------------------------------------------------------------
// out[r,c,m,n] = bin[m,n]; inner period 196 floats = 49 float4s exactly.
// Total float4 = 1,605,632 = 2 * 802,816; 802,816 = 16384*49, so both
// stores of a thread use the SAME sb entry.
__global__ void broadcast_kernel(float4* __restrict__ out) {
    __shared__ float4 sb[49];
    if (threadIdx.x < 49)
        sb[threadIdx.x] = ((const float4*)g_bin)[threadIdx.x];
    __syncthreads();
    const int j = blockIdx.x * blockDim.x + threadIdx.x;   // 0..802815
    const float4 v = sb[j % 49];
    out[j] = v;
    out[j + 802816] = v;
}

// -------------------------------------------------------------------------
extern "C" void kernel_launch(void* const* d_in, const int* in_sizes, int n_in,
                              void* d_out, int out_size) {
    const float* feature = (const float*)d_in[0]; // [1,256,200,320]
    const float* rois    = (const float*)d_in[1]; // [128,4]
    float* out           = (float*)d_out;         // [128,256,14,14]
    (void)in_sizes; (void)n_in; (void)out_size;

    convert_kernel<<<dim3(HWSZ / 32, CC / 64), dim3(32, 8)>>>(feature);
    screen_kernel<<<dim3(NBIN, 8), 256>>>(rois);
    refine_kernel<<<NBIN, 256>>>(feature, rois);
    broadcast_kernel<<<802816 / 256, 256>>>((float4*)out);
}